// round 13
// baseline (speedup 1.0000x reference)
#include <cuda_runtime.h>
#include <cuda_fp16.h>

#define D_FEAT 64
#define MAX_NODES 100000

// Scratch (static __device__ arrays -- no allocation).
__device__ int   g_row_ptr[MAX_NODES + 1];
__device__ uint2 g_x16[MAX_NODES * 16];   // fp16 rows: 128B = 16 x uint2 per row

// Fused prep: blocks [0, rp_blocks) build row_ptr from the sorted targets;
// remaining blocks convert x (f32) -> g_x16 (fp16), lane-strided coalesced.
__global__ __launch_bounds__(256) void prep_kernel(
    const float4* __restrict__ xf4, int n_f4,
    const int* __restrict__ tgt, int n_edges, int n_nodes, int rp_blocks)
{
    const int b = (int)blockIdx.x;
    if (b < rp_blocks) {
        const int e = b * 256 + threadIdx.x;
        if (e >= n_edges) return;
        const int cur  = __ldg(tgt + e);
        const int prev = (e == 0) ? -1 : __ldg(tgt + e - 1);
        for (int v = prev + 1; v <= cur; ++v) g_row_ptr[v] = e;
        if (e == n_edges - 1) {
            for (int v = cur + 1; v <= n_nodes; ++v) g_row_ptr[v] = n_edges;
        }
    } else {
        // 4 float4 per thread, lane-strided (+32) -> fully coalesced LDG.128.
        const int t0 = (b - rp_blocks) * 256 + threadIdx.x;
        const int base = (t0 >> 5) * 128 + (t0 & 31);
        #pragma unroll 4
        for (int k = 0; k < 4; ++k) {
            const int i = base + k * 32;
            if (i < n_f4) {
                const float4 a = __ldg(xf4 + i);
                __half2 h0 = __floats2half2_rn(a.x, a.y);
                __half2 h1 = __floats2half2_rn(a.z, a.w);
                uint2 o;
                o.x = *reinterpret_cast<unsigned int*>(&h0);
                o.y = *reinterpret_cast<unsigned int*>(&h1);
                g_x16[i] = o;
            }
        }
    }
}

__device__ __forceinline__ float2 f2ofbits(unsigned int u) {
    return __half22float2(*reinterpret_cast<__half2*>(&u));
}

// One warp per output node; the WHOLE warp serves one edge at a time.
// fp16 row = 128B = 32 lanes x 4B: lane l owns features (2l, 2l+1) as one
// half2 -> per edge just 2 SHFL + 1 IADD + 1 LDG.32 + 2 F2F + 2 FFMA
// (~8 slots vs 11 for the half-warp layout), 1 temp reg per in-flight load
// -> 8 edges in flight at ~8 temp regs. No cross-lane reduction at all:
// every lane stores its own float2. f32 accumulation.
__global__ __launch_bounds__(128) void mp_gather_kernel(
    const float* __restrict__ ev,   // [n_edges]
    const int*   __restrict__ src,  // [n_edges]
    float*       __restrict__ out,  // [n_nodes, 64]
    int n_nodes)
{
    const int warp = (blockIdx.x * blockDim.x + threadIdx.x) >> 5;
    if (warp >= n_nodes) return;
    const int lane  = threadIdx.x & 31;
    const int lane4 = lane << 2;          // byte offset of this lane's half2
    const int node  = warp;

    const int start = __ldg(&g_row_ptr[node]);
    const int end   = __ldg(&g_row_ptr[node + 1]);

    const char* __restrict__ xb = (const char*)g_x16;  // row s at byte s*128
    float ax = 0.f, ay = 0.f;

    for (int base = start; base < end; base += 32) {
        const int cnt = min(32, end - base);
        // Cooperative metadata load: lane l owns edge base+l of this batch.
        // Source index is pre-shifted to a byte row offset (s * 128).
        int   s_l = 0;
        float w_l = 0.f;
        if (lane < cnt) {
            s_l = __ldg(src + base + lane) << 7;
            w_l = __ldg(ev  + base + lane);
        }

        int k = 0;
        // Main path: 8 edges in flight (8 x LDG.32, 1 temp reg each).
        for (; k + 8 <= cnt; k += 8) {
            const int o0 = __shfl_sync(0xffffffffu, s_l, k + 0) + lane4;
            const int o1 = __shfl_sync(0xffffffffu, s_l, k + 1) + lane4;
            const int o2 = __shfl_sync(0xffffffffu, s_l, k + 2) + lane4;
            const int o3 = __shfl_sync(0xffffffffu, s_l, k + 3) + lane4;
            const int o4 = __shfl_sync(0xffffffffu, s_l, k + 4) + lane4;
            const int o5 = __shfl_sync(0xffffffffu, s_l, k + 5) + lane4;
            const int o6 = __shfl_sync(0xffffffffu, s_l, k + 6) + lane4;
            const int o7 = __shfl_sync(0xffffffffu, s_l, k + 7) + lane4;
            const unsigned int u0 = __ldg((const unsigned int*)(xb + o0));
            const unsigned int u1 = __ldg((const unsigned int*)(xb + o1));
            const unsigned int u2 = __ldg((const unsigned int*)(xb + o2));
            const unsigned int u3 = __ldg((const unsigned int*)(xb + o3));
            const unsigned int u4 = __ldg((const unsigned int*)(xb + o4));
            const unsigned int u5 = __ldg((const unsigned int*)(xb + o5));
            const unsigned int u6 = __ldg((const unsigned int*)(xb + o6));
            const unsigned int u7 = __ldg((const unsigned int*)(xb + o7));
            const float w0 = __shfl_sync(0xffffffffu, w_l, k + 0);
            const float w1 = __shfl_sync(0xffffffffu, w_l, k + 1);
            const float w2 = __shfl_sync(0xffffffffu, w_l, k + 2);
            const float w3 = __shfl_sync(0xffffffffu, w_l, k + 3);
            const float w4 = __shfl_sync(0xffffffffu, w_l, k + 4);
            const float w5 = __shfl_sync(0xffffffffu, w_l, k + 5);
            const float w6 = __shfl_sync(0xffffffffu, w_l, k + 6);
            const float w7 = __shfl_sync(0xffffffffu, w_l, k + 7);
            float2 f;
            f = f2ofbits(u0); ax = fmaf(w0, f.x, ax); ay = fmaf(w0, f.y, ay);
            f = f2ofbits(u1); ax = fmaf(w1, f.x, ax); ay = fmaf(w1, f.y, ay);
            f = f2ofbits(u2); ax = fmaf(w2, f.x, ax); ay = fmaf(w2, f.y, ay);
            f = f2ofbits(u3); ax = fmaf(w3, f.x, ax); ay = fmaf(w3, f.y, ay);
            f = f2ofbits(u4); ax = fmaf(w4, f.x, ax); ay = fmaf(w4, f.y, ay);
            f = f2ofbits(u5); ax = fmaf(w5, f.x, ax); ay = fmaf(w5, f.y, ay);
            f = f2ofbits(u6); ax = fmaf(w6, f.x, ax); ay = fmaf(w6, f.y, ay);
            f = f2ofbits(u7); ax = fmaf(w7, f.x, ax); ay = fmaf(w7, f.y, ay);
        }
        // Tail: one edge at a time (<= 7).
        for (; k < cnt; ++k) {
            const int   o = __shfl_sync(0xffffffffu, s_l, k) + lane4;
            const float w = __shfl_sync(0xffffffffu, w_l, k);
            const unsigned int u = __ldg((const unsigned int*)(xb + o));
            const float2 f = f2ofbits(u);
            ax = fmaf(w, f.x, ax);
            ay = fmaf(w, f.y, ay);
        }
    }

    // Every lane stores its own feature pair: 32 x 8B = 256B coalesced.
    float2* __restrict__ of2 = (float2*)out;
    of2[(size_t)node * 32 + lane] = make_float2(ax, ay);
}

extern "C" void kernel_launch(void* const* d_in, const int* in_sizes, int n_in,
                              void* d_out, int out_size) {
    const float* x   = (const float*)d_in[0];
    const float* ev  = (const float*)d_in[1];
    const int*   tgt = (const int*)d_in[2];
    const int*   src = (const int*)d_in[3];
    float* out = (float*)d_out;

    const int n_edges = in_sizes[1];
    const int n_nodes = out_size / D_FEAT;
    const int n_f4    = n_nodes * (D_FEAT / 4);

    const int rp_blocks = (n_edges + 255) / 256;
    const int cv_blocks = (n_f4 + 1023) / 1024;      // 4 float4/thread
    prep_kernel<<<rp_blocks + cv_blocks, 256>>>(
        (const float4*)x, n_f4, tgt, n_edges, n_nodes, rp_blocks);

    const int threads = 128;
    const int blocks  = (n_nodes * 32 + threads - 1) / threads;
    mp_gather_kernel<<<blocks, threads>>>(ev, src, out, n_nodes);
}

// round 14
// speedup vs baseline: 1.1520x; 1.1520x over previous
#include <cuda_runtime.h>
#include <cuda_fp16.h>

#define D_FEAT 64
#define MAX_NODES 100000

// Scratch (static __device__ arrays -- no allocation).
__device__ int   g_row_ptr[MAX_NODES + 1];
__device__ uint2 g_x16[MAX_NODES * 16];   // fp16 rows: 128B = 16 x uint2 per row

// Fused prep: blocks [0, rp_blocks) build row_ptr from the sorted targets;
// remaining blocks convert x (f32) -> g_x16 (fp16), lane-strided coalesced.
__global__ __launch_bounds__(256) void prep_kernel(
    const float4* __restrict__ xf4, int n_f4,
    const int* __restrict__ tgt, int n_edges, int n_nodes, int rp_blocks)
{
    const int b = (int)blockIdx.x;
    if (b < rp_blocks) {
        const int e = b * 256 + threadIdx.x;
        if (e >= n_edges) return;
        const int cur  = __ldg(tgt + e);
        const int prev = (e == 0) ? -1 : __ldg(tgt + e - 1);
        for (int v = prev + 1; v <= cur; ++v) g_row_ptr[v] = e;
        if (e == n_edges - 1) {
            for (int v = cur + 1; v <= n_nodes; ++v) g_row_ptr[v] = n_edges;
        }
    } else {
        // 4 float4 per thread, lane-strided (+32) -> fully coalesced LDG.128.
        const int t0 = (b - rp_blocks) * 256 + threadIdx.x;
        const int base = (t0 >> 5) * 128 + (t0 & 31);
        #pragma unroll 4
        for (int k = 0; k < 4; ++k) {
            const int i = base + k * 32;
            if (i < n_f4) {
                const float4 a = __ldg(xf4 + i);
                __half2 h0 = __floats2half2_rn(a.x, a.y);
                __half2 h1 = __floats2half2_rn(a.z, a.w);
                uint2 o;
                o.x = *reinterpret_cast<unsigned int*>(&h0);
                o.y = *reinterpret_cast<unsigned int*>(&h1);
                g_x16[i] = o;
            }
        }
    }
}

__device__ __forceinline__ float2 f2ofbits(unsigned int u) {
    return __half22float2(*reinterpret_cast<__half2*>(&u));
}

// One warp per output node; the WHOLE warp serves one edge at a time.
// fp16 row = 128B = 32 lanes x 4B: lane l owns features (2l, 2l+1) as one
// half2 -> per edge: 1 SHFL(s) + 1 IADD + 1 LDG.32 + 1 SHFL(w) + 2 F2F +
// 2 FFMA (~8 slots vs 11 for the half-warp layout). Unroll 4 (NOT 8 --
// R13 showed 8-deep keeps ~24 temps live -> 40 regs -> occ 62%): 12 live
// temps -> ~32 regs -> occ ~84%. No cross-lane reduction; each lane stores
// its own float2. f32 accumulation.
__global__ __launch_bounds__(128) void mp_gather_kernel(
    const float* __restrict__ ev,   // [n_edges]
    const int*   __restrict__ src,  // [n_edges]
    float*       __restrict__ out,  // [n_nodes, 64]
    int n_nodes)
{
    const int warp = (blockIdx.x * blockDim.x + threadIdx.x) >> 5;
    if (warp >= n_nodes) return;
    const int lane  = threadIdx.x & 31;
    const int lane4 = lane << 2;          // byte offset of this lane's half2
    const int node  = warp;

    const int start = __ldg(&g_row_ptr[node]);
    const int end   = __ldg(&g_row_ptr[node + 1]);

    const char* __restrict__ xb = (const char*)g_x16;  // row s at byte s*128
    float ax = 0.f, ay = 0.f;

    for (int base = start; base < end; base += 32) {
        const int cnt = min(32, end - base);
        // Cooperative metadata load: lane l owns edge base+l of this batch.
        // Source index pre-shifted to a byte row offset (s * 128).
        int   s_l = 0;
        float w_l = 0.f;
        if (lane < cnt) {
            s_l = __ldg(src + base + lane) << 7;
            w_l = __ldg(ev  + base + lane);
        }

        int k = 0;
        // Main path: 4 edges in flight (4 x LDG.32, 12 live temps).
        for (; k + 4 <= cnt; k += 4) {
            const int o0 = __shfl_sync(0xffffffffu, s_l, k + 0) + lane4;
            const int o1 = __shfl_sync(0xffffffffu, s_l, k + 1) + lane4;
            const int o2 = __shfl_sync(0xffffffffu, s_l, k + 2) + lane4;
            const int o3 = __shfl_sync(0xffffffffu, s_l, k + 3) + lane4;
            const unsigned int u0 = __ldg((const unsigned int*)(xb + o0));
            const unsigned int u1 = __ldg((const unsigned int*)(xb + o1));
            const unsigned int u2 = __ldg((const unsigned int*)(xb + o2));
            const unsigned int u3 = __ldg((const unsigned int*)(xb + o3));
            const float w0 = __shfl_sync(0xffffffffu, w_l, k + 0);
            const float w1 = __shfl_sync(0xffffffffu, w_l, k + 1);
            const float w2 = __shfl_sync(0xffffffffu, w_l, k + 2);
            const float w3 = __shfl_sync(0xffffffffu, w_l, k + 3);
            float2 f;
            f = f2ofbits(u0); ax = fmaf(w0, f.x, ax); ay = fmaf(w0, f.y, ay);
            f = f2ofbits(u1); ax = fmaf(w1, f.x, ax); ay = fmaf(w1, f.y, ay);
            f = f2ofbits(u2); ax = fmaf(w2, f.x, ax); ay = fmaf(w2, f.y, ay);
            f = f2ofbits(u3); ax = fmaf(w3, f.x, ax); ay = fmaf(w3, f.y, ay);
        }
        // Tail: one edge at a time (<= 3).
        for (; k < cnt; ++k) {
            const int   o = __shfl_sync(0xffffffffu, s_l, k) + lane4;
            const float w = __shfl_sync(0xffffffffu, w_l, k);
            const unsigned int u = __ldg((const unsigned int*)(xb + o));
            const float2 f = f2ofbits(u);
            ax = fmaf(w, f.x, ax);
            ay = fmaf(w, f.y, ay);
        }
    }

    // Every lane stores its own feature pair: 32 x 8B = 256B coalesced.
    float2* __restrict__ of2 = (float2*)out;
    of2[(size_t)node * 32 + lane] = make_float2(ax, ay);
}

extern "C" void kernel_launch(void* const* d_in, const int* in_sizes, int n_in,
                              void* d_out, int out_size) {
    const float* x   = (const float*)d_in[0];
    const float* ev  = (const float*)d_in[1];
    const int*   tgt = (const int*)d_in[2];
    const int*   src = (const int*)d_in[3];
    float* out = (float*)d_out;

    const int n_edges = in_sizes[1];
    const int n_nodes = out_size / D_FEAT;
    const int n_f4    = n_nodes * (D_FEAT / 4);

    const int rp_blocks = (n_edges + 255) / 256;
    const int cv_blocks = (n_f4 + 1023) / 1024;      // 4 float4/thread
    prep_kernel<<<rp_blocks + cv_blocks, 256>>>(
        (const float4*)x, n_f4, tgt, n_edges, n_nodes, rp_blocks);

    const int threads = 128;
    const int blocks  = (n_nodes * 32 + threads - 1) / threads;
    mp_gather_kernel<<<blocks, threads>>>(ev, src, out, n_nodes);
}

// round 15
// speedup vs baseline: 1.1588x; 1.0059x over previous
#include <cuda_runtime.h>

#define D_FEAT 64
#define MAX_NODES 100000

// Scratch (static __device__ array -- no allocation).
__device__ int g_row_ptr[MAX_NODES + 1];

// Build row_ptr from the sorted target index: row_ptr[v] = first edge e with
// tgt[e] >= v. Boundary ranges are disjoint across e -> race-free writes.
__global__ __launch_bounds__(256) void build_row_ptr_kernel(
    const int* __restrict__ tgt, int n_edges, int n_nodes)
{
    const int e = blockIdx.x * blockDim.x + threadIdx.x;
    if (e >= n_edges) return;
    const int cur  = __ldg(tgt + e);
    const int prev = (e == 0) ? -1 : __ldg(tgt + e - 1);
    for (int v = prev + 1; v <= cur; ++v) g_row_ptr[v] = e;
    if (e == n_edges - 1) {
        for (int v = cur + 1; v <= n_nodes; ++v) g_row_ptr[v] = n_edges;
    }
}

// One warp per output node; the WHOLE warp serves one edge at a time,
// reading x in f32 directly (no fp16 staging => no prep convert pass, no
// F2F in the inner loop). f32 row = 256B = 32 lanes x float2: lane l owns
// features (2l, 2l+1). Per edge: 1 SHFL(s) + 1 IADD + 1 LDG.64 + 1 SHFL(w)
// + 2 FFMA (~6 slots). Unroll 4 => 4 edges in flight, ~16 live temps
// (4 offsets + 4 float2 + 4 weights) -> regs ~34-36, occ ~80%.
// No cross-lane reduction; each lane stores its own float2.
__global__ __launch_bounds__(128) void mp_gather_kernel(
    const float* __restrict__ x,    // [n_nodes, 64]
    const float* __restrict__ ev,   // [n_edges]
    const int*   __restrict__ src,  // [n_edges]
    float*       __restrict__ out,  // [n_nodes, 64]
    int n_nodes)
{
    const int warp = (blockIdx.x * blockDim.x + threadIdx.x) >> 5;
    if (warp >= n_nodes) return;
    const int lane  = threadIdx.x & 31;
    const int lane8 = lane << 3;          // byte offset of this lane's float2
    const int node  = warp;

    const int start = __ldg(&g_row_ptr[node]);
    const int end   = __ldg(&g_row_ptr[node + 1]);

    const char* __restrict__ xb = (const char*)x;   // row s at byte s*256
    float ax = 0.f, ay = 0.f;

    for (int base = start; base < end; base += 32) {
        const int cnt = min(32, end - base);
        // Cooperative metadata load: lane l owns edge base+l of this batch.
        // Source index pre-shifted to a byte row offset (s * 256).
        int   s_l = 0;
        float w_l = 0.f;
        if (lane < cnt) {
            s_l = __ldg(src + base + lane) << 8;
            w_l = __ldg(ev  + base + lane);
        }

        int k = 0;
        // Main path: 4 edges in flight (4 x LDG.64).
        for (; k + 4 <= cnt; k += 4) {
            const int o0 = __shfl_sync(0xffffffffu, s_l, k + 0) + lane8;
            const int o1 = __shfl_sync(0xffffffffu, s_l, k + 1) + lane8;
            const int o2 = __shfl_sync(0xffffffffu, s_l, k + 2) + lane8;
            const int o3 = __shfl_sync(0xffffffffu, s_l, k + 3) + lane8;
            const float2 f0 = __ldg((const float2*)(xb + o0));
            const float2 f1 = __ldg((const float2*)(xb + o1));
            const float2 f2 = __ldg((const float2*)(xb + o2));
            const float2 f3 = __ldg((const float2*)(xb + o3));
            const float w0 = __shfl_sync(0xffffffffu, w_l, k + 0);
            const float w1 = __shfl_sync(0xffffffffu, w_l, k + 1);
            const float w2 = __shfl_sync(0xffffffffu, w_l, k + 2);
            const float w3 = __shfl_sync(0xffffffffu, w_l, k + 3);
            ax = fmaf(w0, f0.x, ax); ay = fmaf(w0, f0.y, ay);
            ax = fmaf(w1, f1.x, ax); ay = fmaf(w1, f1.y, ay);
            ax = fmaf(w2, f2.x, ax); ay = fmaf(w2, f2.y, ay);
            ax = fmaf(w3, f3.x, ax); ay = fmaf(w3, f3.y, ay);
        }
        // Tail: one edge at a time (<= 3).
        for (; k < cnt; ++k) {
            const int   o = __shfl_sync(0xffffffffu, s_l, k) + lane8;
            const float w = __shfl_sync(0xffffffffu, w_l, k);
            const float2 f = __ldg((const float2*)(xb + o));
            ax = fmaf(w, f.x, ax);
            ay = fmaf(w, f.y, ay);
        }
    }

    // Every lane stores its own feature pair: 32 x 8B = 256B coalesced.
    float2* __restrict__ of2 = (float2*)out;
    of2[(size_t)node * 32 + lane] = make_float2(ax, ay);
}

extern "C" void kernel_launch(void* const* d_in, const int* in_sizes, int n_in,
                              void* d_out, int out_size) {
    const float* x   = (const float*)d_in[0];
    const float* ev  = (const float*)d_in[1];
    const int*   tgt = (const int*)d_in[2];
    const int*   src = (const int*)d_in[3];
    float* out = (float*)d_out;

    const int n_edges = in_sizes[1];
    const int n_nodes = out_size / D_FEAT;

    build_row_ptr_kernel<<<(n_edges + 255) / 256, 256>>>(tgt, n_edges, n_nodes);

    const int threads = 128;
    const int blocks  = (n_nodes * 32 + threads - 1) / threads;
    mp_gather_kernel<<<blocks, threads>>>(x, ev, src, out, n_nodes);
}